// round 7
// baseline (speedup 1.0000x reference)
#include <cuda_runtime.h>
#include <math.h>
#include <float.h>

#define TEMP_INV (1.0f / 0.07f)
#define ALPHA 0.4f
#define BETA  0.2f
#define LAMBDA 0.2f
#define MAXB 8192

// Per-sample scratch (allocation-free: __device__ globals).
// All values are pre-masked by validity so finalize is a plain sum.
__device__ float g_ce[MAXB];     // ce(l_pos), 0 if invalid
__device__ float g_cenb[MAXB];   // ce(l_pos_nb), 0 if invalid
__device__ float g_bml[MAXB];    // bml, 0 if not bml_valid
__device__ float g_val[MAXB];    // 1 if hn_count>0
__device__ float g_bval[MAXB];   // 1 if hn_count>0 && fn_count>0

// Dot of a 512-float row against q (in smem), one warp per row.
// Coalesced: lane i loads float4 at [i, i+32, i+64, i+96].
__device__ __forceinline__ float row_dot512(const float4* __restrict__ row,
                                            const float4* sq, int lane) {
    float acc = 0.f;
#pragma unroll
    for (int j = 0; j < 4; j++) {
        float4 a = row[lane + 32 * j];
        float4 b = sq[lane + 32 * j];
        acc = fmaf(a.x, b.x, fmaf(a.y, b.y, fmaf(a.z, b.z, fmaf(a.w, b.w, acc))));
    }
#pragma unroll
    for (int o = 16; o; o >>= 1) acc += __shfl_xor_sync(0xffffffffu, acc, o);
    return acc;  // same value in all 32 lanes
}

__global__ __launch_bounds__(256, 8) void cluster_loss_main(
    const float* __restrict__ q,  const float* __restrict__ k,
    const float* __restrict__ k2, const float* __restrict__ hn,
    const float* __restrict__ fn, const int* __restrict__ hnc,
    const int* __restrict__ fnc,  int NMAX, int MMAX)
{
    const int b = blockIdx.x;
    __shared__ float4 sq[128];                 // q[b], 512 floats
    __shared__ float s_m[8], s_s[8], s_fn[8];  // per-warp partials
    __shared__ float s_dk, s_dk2;

    const int tid = threadIdx.x, wid = tid >> 5, lane = tid & 31;

    const float4* q4 = (const float4*)(q + (size_t)b * 512);
    if (tid < 128) sq[tid] = q4[tid];
    __syncthreads();

    const int ch = hnc[b];
    const int cf = fnc[b];
    const int ntasks = 2 + cf + ch;   // task 0: k, task 1: k2, then fn rows, then hn rows

    const float4* hn4 = (const float4*)(hn + (size_t)b * NMAX * 512);
    const float4* fn4 = (const float4*)(fn + (size_t)b * MMAX * 512);
    const float4* k4  = (const float4*)(k  + (size_t)b * 512);
    const float4* k24 = (const float4*)(k2 + (size_t)b * 512);

    // warp-local online-logsumexp state + fn-dot sum
    float m = -FLT_MAX, s = 0.f, fs = 0.f;

    for (int t = wid; t < ntasks; t += 8) {
        const float4* row;
        if      (t == 0)      row = k4;
        else if (t == 1)      row = k24;
        else if (t < 2 + cf)  row = fn4 + (size_t)(t - 2) * 128;
        else                  row = hn4 + (size_t)(t - 2 - cf) * 128;

        float d = row_dot512(row, sq, lane);

        if      (t == 0)      { if (lane == 0) s_dk  = d; }
        else if (t == 1)      { if (lane == 0) s_dk2 = d; }
        else if (t < 2 + cf)  { fs += d; }
        else {
            float l  = d * TEMP_INV;
            float nm = fmaxf(m, l);
            s = s * __expf(m - nm) + __expf(l - nm);  // exp(-FLT_MAX-x) -> 0, safe
            m = nm;
        }
    }

    if (lane == 0) { s_m[wid] = m; s_s[wid] = s; s_fn[wid] = fs; }
    __syncthreads();

    if (tid == 0) {
        // combine 8 warp-local (m, s) pairs + fn sums
        float M = -FLT_MAX, S = 0.f, F = 0.f;
#pragma unroll
        for (int w = 0; w < 8; w++) {
            float wm = s_m[w];
            float nm = fmaxf(M, wm);
            S = S * __expf(M - nm) + s_s[w] * __expf(wm - nm);
            M = nm;
            F += s_fn[w];
        }

        const bool valid = (ch > 0);
        const float dk = s_dk, dk2 = s_dk2;
        float ce = 0.f, cenb = 0.f;
        if (valid) {
            float lse  = M + logf(S);           // logsumexp over valid hn rows
            float lp   = dk  * TEMP_INV;
            float lpnb = dk2 * TEMP_INV;
            // logaddexp(lp, lse) - lp, numerically stable
            float mx = fmaxf(lp, lse);
            ce   = mx + log1pf(expf(-fabsf(lp - lse)))   - lp;
            mx = fmaxf(lpnb, lse);
            cenb = mx + log1pf(expf(-fabsf(lpnb - lse))) - lpnb;
        }

        float simfn = F / (float)max(cf, 1);
        float delta = simfn - dk;               // sim_pos = q·k (no temperature)
        float bml   = fmaxf(delta + ALPHA, 0.f) + fmaxf(-delta - BETA, 0.f);
        const bool bv = valid && (cf > 0);

        g_ce[b]   = ce;
        g_cenb[b] = cenb;
        g_bml[b]  = bv ? bml : 0.f;
        g_val[b]  = valid ? 1.f : 0.f;
        g_bval[b] = bv ? 1.f : 0.f;
    }
}

__global__ __launch_bounds__(256) void cluster_loss_finalize(
    float* __restrict__ out, int B, int out_size)
{
    __shared__ float sh[5][256];
    const int tid = threadIdx.x;
    float a0 = 0.f, a1 = 0.f, a2 = 0.f, a3 = 0.f, a4 = 0.f;
    for (int b = tid; b < B; b += 256) {
        a0 += g_ce[b]; a1 += g_cenb[b]; a2 += g_bml[b];
        a3 += g_val[b]; a4 += g_bval[b];
    }
    sh[0][tid] = a0; sh[1][tid] = a1; sh[2][tid] = a2;
    sh[3][tid] = a3; sh[4][tid] = a4;
    __syncthreads();
#pragma unroll
    for (int o = 128; o; o >>= 1) {
        if (tid < o) {
#pragma unroll
            for (int i = 0; i < 5; i++) sh[i][tid] += sh[i][tid + o];
        }
        __syncthreads();
    }
    if (tid == 0) {
        float nval  = fmaxf(sh[3][0], 1.f);
        float cl    = sh[0][0] / nval;
        float clnb  = sh[1][0] / nval;
        float nbml  = sh[4][0];
        float bmlm  = (nbml > 0.f) ? (sh[2][0] / nbml) : 0.f;
        float lbml  = LAMBDA * bmlm;
        float tot   = cl + clnb + lbml;
        if (out_size > 0) out[0] = tot;
        if (out_size > 1) out[1] = cl;
        if (out_size > 2) out[2] = lbml;
        if (out_size > 3) out[3] = clnb;
    }
}

extern "C" void kernel_launch(void* const* d_in, const int* in_sizes, int n_in,
                              void* d_out, int out_size) {
    const float* q   = (const float*)d_in[0];
    const float* k   = (const float*)d_in[1];
    const float* k2  = (const float*)d_in[2];
    const float* hn  = (const float*)d_in[3];
    const float* fn  = (const float*)d_in[4];
    const int*   hnc = (const int*)d_in[5];
    const int*   fnc = (const int*)d_in[6];

    int B = in_sizes[5];                 // hn_counts element count
    int D = in_sizes[0] / B;             // 512
    int NMAX = in_sizes[3] / (B * D);    // 256
    int MMAX = in_sizes[4] / (B * D);    // 32

    cluster_loss_main<<<B, 256>>>(q, k, k2, hn, fn, hnc, fnc, NMAX, MMAX);
    cluster_loss_finalize<<<1, 256>>>((float*)d_out, B, out_size);
}

// round 8
// speedup vs baseline: 1.1403x; 1.1403x over previous
#include <cuda_runtime.h>
#include <math.h>
#include <float.h>

#define TEMP_INV (1.0f / 0.07f)
#define ALPHA 0.4f
#define BETA  0.2f
#define LAMBDA 0.2f
#define MAXB 4096
#define MAXC 8
#define CHUNK 32   // hn rows per chunk-CTA

// Per-(sample,chunk) partial state (allocation-free scratch).
__device__ float g_m[MAXB * MAXC];   // chunk-local LSE max
__device__ float g_s[MAXB * MAXC];   // chunk-local LSE sum (relative to g_m)
__device__ float g_f[MAXB * MAXC];   // chunk-local fn-dot partial sum
__device__ float g_dk[MAXB];         // q·k   (written by chunk 0)
__device__ float g_dk2[MAXB];        // q·k2  (written by chunk 1)

// Dot of a 512-float row against q (in smem), one warp per row.
// Streaming loads (evict-first): hn/fn are read exactly once.
__device__ __forceinline__ float row_dot512(const float4* __restrict__ row,
                                            const float4* sq, int lane) {
    float acc = 0.f;
#pragma unroll
    for (int j = 0; j < 4; j++) {
        float4 a = __ldcs(row + lane + 32 * j);
        float4 b = sq[lane + 32 * j];
        acc = fmaf(a.x, b.x, fmaf(a.y, b.y, fmaf(a.z, b.z, fmaf(a.w, b.w, acc))));
    }
#pragma unroll
    for (int o = 16; o; o >>= 1) acc += __shfl_xor_sync(0xffffffffu, acc, o);
    return acc;
}

// grid: (C, B). CTA (c, b) handles hn rows [c*CHUNK, c*CHUNK+CHUNK) of sample b,
// fn rows [c*FCH, c*FCH+FCH), plus k (c==0) / k2 (c==1).
__global__ __launch_bounds__(256, 8) void cluster_loss_main(
    const float* __restrict__ q,  const float* __restrict__ k,
    const float* __restrict__ k2, const float* __restrict__ hn,
    const float* __restrict__ fn, const int* __restrict__ hnc,
    const int* __restrict__ fnc,  int NMAX, int MMAX, int C, int FCH)
{
    const int c = blockIdx.x;
    const int b = blockIdx.y;
    const int tid = threadIdx.x, wid = tid >> 5, lane = tid & 31;

    const int ch = hnc[b];
    const int cf = fnc[b];

    const int extra = (c < 2) ? 1 : 0;               // k or k2 task
    const int f0 = c * FCH;
    const int nf = min(max(cf - f0, 0), FCH);
    const int h0 = c * CHUNK;
    const int nh = min(max(ch - h0, 0), CHUNK);
    const int ntasks = extra + nf + nh;
    const int idx = b * C + c;

    if (ntasks == 0) {
        if (tid == 0) { g_m[idx] = -FLT_MAX; g_s[idx] = 0.f; g_f[idx] = 0.f; }
        return;
    }

    __shared__ float4 sq[128];
    __shared__ float s_m[8], s_s[8], s_fn[8];

    const float4* q4 = (const float4*)(q + (size_t)b * 512);
    if (tid < 128) sq[tid] = q4[tid];
    __syncthreads();

    const float4* hn4 = (const float4*)(hn + ((size_t)b * NMAX + h0) * 512);
    const float4* fn4 = (const float4*)(fn + ((size_t)b * MMAX + f0) * 512);
    const float4* kx4 = (const float4*)(((c == 0) ? k : k2) + (size_t)b * 512);

    float m = -FLT_MAX, s = 0.f, fs = 0.f;
    float dkx = 0.f;

    for (int t = wid; t < ntasks; t += 8) {
        const float4* row;
        if      (t < extra)      row = kx4;
        else if (t < extra + nf) row = fn4 + (size_t)(t - extra) * 128;
        else                     row = hn4 + (size_t)(t - extra - nf) * 128;

        float d = row_dot512(row, sq, lane);

        if      (t < extra)      { dkx = d; }
        else if (t < extra + nf) { fs += d; }
        else {
            float l  = d * TEMP_INV;
            float nm = fmaxf(m, l);
            s = s * __expf(m - nm) + __expf(l - nm);
            m = nm;
        }
    }

    // warp 0, lane 0 held the k/k2 task (t == 0 only occurs in warp 0)
    if (wid == 0 && lane == 0 && extra) {
        if (c == 0) g_dk[b] = dkx; else g_dk2[b] = dkx;
    }

    if (lane == 0) { s_m[wid] = m; s_s[wid] = s; s_fn[wid] = fs; }
    __syncthreads();

    if (tid == 0) {
        float M = -FLT_MAX, S = 0.f, F = 0.f;
#pragma unroll
        for (int w = 0; w < 8; w++) {
            float wm = s_m[w];
            float nm = fmaxf(M, wm);
            S = S * __expf(M - nm) + s_s[w] * __expf(wm - nm);
            M = nm;
            F += s_fn[w];
        }
        g_m[idx] = M; g_s[idx] = S; g_f[idx] = F;
    }
}

__global__ __launch_bounds__(256) void cluster_loss_finalize(
    float* __restrict__ out, const int* __restrict__ hnc,
    const int* __restrict__ fnc, int B, int C, int out_size)
{
    __shared__ float sh[5][256];
    const int tid = threadIdx.x;
    float a0 = 0.f, a1 = 0.f, a2 = 0.f, a3 = 0.f, a4 = 0.f;

    for (int b = tid; b < B; b += 256) {
        const int ch = hnc[b];
        const int cf = fnc[b];

        // combine chunk partials in fixed order (deterministic)
        float M = -FLT_MAX, S = 0.f, F = 0.f;
        for (int c = 0; c < C; c++) {
            int i = b * C + c;
            float cm = g_m[i];
            float nm = fmaxf(M, cm);
            S = S * __expf(M - nm) + g_s[i] * __expf(cm - nm);
            M = nm;
            F += g_f[i];
        }

        const bool valid = (ch > 0);
        const float dk = g_dk[b], dk2 = g_dk2[b];
        float ce = 0.f, cenb = 0.f;
        if (valid) {
            float lse  = M + logf(S);
            float lp   = dk  * TEMP_INV;
            float lpnb = dk2 * TEMP_INV;
            float mx = fmaxf(lp, lse);
            ce   = mx + log1pf(expf(-fabsf(lp - lse)))   - lp;
            mx = fmaxf(lpnb, lse);
            cenb = mx + log1pf(expf(-fabsf(lpnb - lse))) - lpnb;
        }

        float simfn = F / (float)max(cf, 1);
        float delta = simfn - dk;
        float bml   = fmaxf(delta + ALPHA, 0.f) + fmaxf(-delta - BETA, 0.f);
        const bool bv = valid && (cf > 0);

        a0 += ce;
        a1 += cenb;
        a2 += bv ? bml : 0.f;
        a3 += valid ? 1.f : 0.f;
        a4 += bv ? 1.f : 0.f;
    }

    sh[0][tid] = a0; sh[1][tid] = a1; sh[2][tid] = a2;
    sh[3][tid] = a3; sh[4][tid] = a4;
    __syncthreads();
#pragma unroll
    for (int o = 128; o; o >>= 1) {
        if (tid < o) {
#pragma unroll
            for (int i = 0; i < 5; i++) sh[i][tid] += sh[i][tid + o];
        }
        __syncthreads();
    }
    if (tid == 0) {
        float nval  = fmaxf(sh[3][0], 1.f);
        float cl    = sh[0][0] / nval;
        float clnb  = sh[1][0] / nval;
        float nbml  = sh[4][0];
        float bmlm  = (nbml > 0.f) ? (sh[2][0] / nbml) : 0.f;
        float lbml  = LAMBDA * bmlm;
        float tot   = cl + clnb + lbml;
        if (out_size > 0) out[0] = tot;
        if (out_size > 1) out[1] = cl;
        if (out_size > 2) out[2] = lbml;
        if (out_size > 3) out[3] = clnb;
    }
}

extern "C" void kernel_launch(void* const* d_in, const int* in_sizes, int n_in,
                              void* d_out, int out_size) {
    const float* q   = (const float*)d_in[0];
    const float* k   = (const float*)d_in[1];
    const float* k2  = (const float*)d_in[2];
    const float* hn  = (const float*)d_in[3];
    const float* fn  = (const float*)d_in[4];
    const int*   hnc = (const int*)d_in[5];
    const int*   fnc = (const int*)d_in[6];

    int B = in_sizes[5];                 // hn_counts element count
    int D = in_sizes[0] / B;             // 512
    int NMAX = in_sizes[3] / (B * D);    // 256
    int MMAX = in_sizes[4] / (B * D);    // 32

    int C = (NMAX + CHUNK - 1) / CHUNK;  // 8
    if (C > MAXC) C = MAXC;              // (shapes are fixed; guard anyway)
    int FCH = (MMAX + C - 1) / C;        // 4

    dim3 grid(C, B);
    cluster_loss_main<<<grid, 256>>>(q, k, k2, hn, fn, hnc, fnc,
                                     NMAX, MMAX, C, FCH);
    cluster_loss_finalize<<<1, 256>>>((float*)d_out, hnc, fnc, B, C, out_size);
}

// round 10
// speedup vs baseline: 1.1597x; 1.0170x over previous
#include <cuda_runtime.h>
#include <math.h>
#include <float.h>

#define TEMP_INV (1.0f / 0.07f)
#define ALPHA 0.4f
#define BETA  0.2f
#define LAMBDA 0.2f
#define MAXB 4096
#define MAXC 8
#define CHUNK 32   // hn rows per chunk-CTA

// Per-(sample,chunk) partial state (allocation-free scratch).
__device__ float g_m[MAXB * MAXC];   // chunk-local LSE max
__device__ float g_s[MAXB * MAXC];   // chunk-local LSE sum (relative to g_m)
__device__ float g_f[MAXB * MAXC];   // chunk-local fn-dot partial sum
__device__ float g_dk[MAXB];         // q·k   (written by chunk 0)
__device__ float g_dk2[MAXB];        // q·k2  (written by chunk 1)

// Dot of a 512-float row against q (in smem), one warp per row.
// Streaming loads (evict-first): hn/fn are read exactly once.
__device__ __forceinline__ float row_dot512(const float4* __restrict__ row,
                                            const float4* sq, int lane) {
    float acc = 0.f;
#pragma unroll
    for (int j = 0; j < 4; j++) {
        float4 a = __ldcs(row + lane + 32 * j);
        float4 b = sq[lane + 32 * j];
        acc = fmaf(a.x, b.x, fmaf(a.y, b.y, fmaf(a.z, b.z, fmaf(a.w, b.w, acc))));
    }
#pragma unroll
    for (int o = 16; o; o >>= 1) acc += __shfl_xor_sync(0xffffffffu, acc, o);
    return acc;
}

// grid: (C, B). CTA (c, b) handles hn rows [c*CHUNK, c*CHUNK+CHUNK) of sample b,
// fn rows [c*FCH, c*FCH+FCH), plus k (c==0) / k2 (c==1).
__global__ __launch_bounds__(256, 8) void cluster_loss_main(
    const float* __restrict__ q,  const float* __restrict__ k,
    const float* __restrict__ k2, const float* __restrict__ hn,
    const float* __restrict__ fn, const int* __restrict__ hnc,
    const int* __restrict__ fnc,  int NMAX, int MMAX, int C, int FCH)
{
    const int c = blockIdx.x;
    const int b = blockIdx.y;
    const int tid = threadIdx.x, wid = tid >> 5, lane = tid & 31;

    const int ch = hnc[b];
    const int cf = fnc[b];

    const int extra = (c < 2) ? 1 : 0;               // k or k2 task
    const int f0 = c * FCH;
    const int nf = min(max(cf - f0, 0), FCH);
    const int h0 = c * CHUNK;
    const int nh = min(max(ch - h0, 0), CHUNK);
    const int ntasks = extra + nf + nh;
    const int idx = b * C + c;

    if (ntasks == 0) {
        if (tid == 0) { g_m[idx] = -FLT_MAX; g_s[idx] = 0.f; g_f[idx] = 0.f; }
        return;
    }

    __shared__ float4 sq[128];
    __shared__ float s_m[8], s_s[8], s_fn[8];

    const float4* q4 = (const float4*)(q + (size_t)b * 512);
    if (tid < 128) sq[tid] = q4[tid];
    __syncthreads();

    const float4* hn4 = (const float4*)(hn + ((size_t)b * NMAX + h0) * 512);
    const float4* fn4 = (const float4*)(fn + ((size_t)b * MMAX + f0) * 512);
    const float4* kx4 = (const float4*)(((c == 0) ? k : k2) + (size_t)b * 512);

    float m = -FLT_MAX, s = 0.f, fs = 0.f;
    float dkx = 0.f;

    for (int t = wid; t < ntasks; t += 8) {
        const float4* row;
        if      (t < extra)      row = kx4;
        else if (t < extra + nf) row = fn4 + (size_t)(t - extra) * 128;
        else                     row = hn4 + (size_t)(t - extra - nf) * 128;

        float d = row_dot512(row, sq, lane);

        if      (t < extra)      { dkx = d; }
        else if (t < extra + nf) { fs += d; }
        else {
            float l  = d * TEMP_INV;
            float nm = fmaxf(m, l);
            s = s * __expf(m - nm) + __expf(l - nm);
            m = nm;
        }
    }

    // warp 0, lane 0 held the k/k2 task (t == 0 only occurs in warp 0)
    if (wid == 0 && lane == 0 && extra) {
        if (c == 0) g_dk[b] = dkx; else g_dk2[b] = dkx;
    }

    if (lane == 0) { s_m[wid] = m; s_s[wid] = s; s_fn[wid] = fs; }
    __syncthreads();

    if (tid == 0) {
        float M = -FLT_MAX, S = 0.f, F = 0.f;
#pragma unroll
        for (int w = 0; w < 8; w++) {
            float wm = s_m[w];
            float nm = fmaxf(M, wm);
            S = S * __expf(M - nm) + s_s[w] * __expf(wm - nm);
            M = nm;
            F += s_fn[w];
        }
        g_m[idx] = M; g_s[idx] = S; g_f[idx] = F;
    }
}

__global__ __launch_bounds__(256) void cluster_loss_finalize(
    float* __restrict__ out, const int* __restrict__ hnc,
    const int* __restrict__ fnc, int B, int C, int out_size)
{
    __shared__ float sh[5][256];
    const int tid = threadIdx.x;
    float a0 = 0.f, a1 = 0.f, a2 = 0.f, a3 = 0.f, a4 = 0.f;

    for (int b = tid; b < B; b += 256) {
        const int ch = hnc[b];
        const int cf = fnc[b];

        // combine chunk partials in fixed order (deterministic)
        float M = -FLT_MAX, S = 0.f, F = 0.f;
        for (int c = 0; c < C; c++) {
            int i = b * C + c;
            float cm = g_m[i];
            float nm = fmaxf(M, cm);
            S = S * __expf(M - nm) + g_s[i] * __expf(cm - nm);
            M = nm;
            F += g_f[i];
        }

        const bool valid = (ch > 0);
        const float dk = g_dk[b], dk2 = g_dk2[b];
        float ce = 0.f, cenb = 0.f;
        if (valid) {
            float lse  = M + logf(S);
            float lp   = dk  * TEMP_INV;
            float lpnb = dk2 * TEMP_INV;
            float mx = fmaxf(lp, lse);
            ce   = mx + log1pf(expf(-fabsf(lp - lse)))   - lp;
            mx = fmaxf(lpnb, lse);
            cenb = mx + log1pf(expf(-fabsf(lpnb - lse))) - lpnb;
        }

        float simfn = F / (float)max(cf, 1);
        float delta = simfn - dk;
        float bml   = fmaxf(delta + ALPHA, 0.f) + fmaxf(-delta - BETA, 0.f);
        const bool bv = valid && (cf > 0);

        a0 += ce;
        a1 += cenb;
        a2 += bv ? bml : 0.f;
        a3 += valid ? 1.f : 0.f;
        a4 += bv ? 1.f : 0.f;
    }

    sh[0][tid] = a0; sh[1][tid] = a1; sh[2][tid] = a2;
    sh[3][tid] = a3; sh[4][tid] = a4;
    __syncthreads();
#pragma unroll
    for (int o = 128; o; o >>= 1) {
        if (tid < o) {
#pragma unroll
            for (int i = 0; i < 5; i++) sh[i][tid] += sh[i][tid + o];
        }
        __syncthreads();
    }
    if (tid == 0) {
        float nval  = fmaxf(sh[3][0], 1.f);
        float cl    = sh[0][0] / nval;
        float clnb  = sh[1][0] / nval;
        float nbml  = sh[4][0];
        float bmlm  = (nbml > 0.f) ? (sh[2][0] / nbml) : 0.f;
        float lbml  = LAMBDA * bmlm;
        float tot   = cl + clnb + lbml;
        if (out_size > 0) out[0] = tot;
        if (out_size > 1) out[1] = cl;
        if (out_size > 2) out[2] = lbml;
        if (out_size > 3) out[3] = clnb;
    }
}

extern "C" void kernel_launch(void* const* d_in, const int* in_sizes, int n_in,
                              void* d_out, int out_size) {
    const float* q   = (const float*)d_in[0];
    const float* k   = (const float*)d_in[1];
    const float* k2  = (const float*)d_in[2];
    const float* hn  = (const float*)d_in[3];
    const float* fn  = (const float*)d_in[4];
    const int*   hnc = (const int*)d_in[5];
    const int*   fnc = (const int*)d_in[6];

    int B = in_sizes[5];                 // hn_counts element count
    int D = in_sizes[0] / B;             // 512
    int NMAX = in_sizes[3] / (B * D);    // 256
    int MMAX = in_sizes[4] / (B * D);    // 32

    int C = (NMAX + CHUNK - 1) / CHUNK;  // 8
    if (C > MAXC) C = MAXC;              // (shapes are fixed; guard anyway)
    int FCH = (MMAX + C - 1) / C;        // 4

    dim3 grid(C, B);
    cluster_loss_main<<<grid, 256>>>(q, k, k2, hn, fn, hnc, fnc,
                                     NMAX, MMAX, C, FCH);
    cluster_loss_finalize<<<1, 256>>>((float*)d_out, hnc, fnc, B, C, out_size);
}